// round 3
// baseline (speedup 1.0000x reference)
#include <cuda_runtime.h>
#include <cstdint>

// Problem constants
#define DMODEL 768
#define NHEADS 12
#define DKH    64
#define NB     2
#define SEQ    4096
#define MTOT   (NB * SEQ)   // 8192
#define DD     (DMODEL * DMODEL)

// within-8 column interleave: logical j -> physical, so that (tg, tg+4) are adjacent
#define PI8(j) (((j) < 4) ? (2 * (j)) : (2 * ((j) - 4) + 1))

#define QSCALE (0.125f * 1.4426950408889634f)  // 1/sqrt(dk) * log2(e)

// Scratch (device globals: allocation-free contract)
__device__ float g_q[NB * NHEADS * SEQ * DKH];   // [bh][s][d'] d-permuted, tf32, prescaled
__device__ float g_k[NB * NHEADS * SEQ * DKH];   // [bh][s][d'] d-permuted, tf32
__device__ float g_v[NB * NHEADS * DKH * SEQ];   // [bh][d][s'] transposed, s-permuted, tf32
__device__ float g_ctx[MTOT * DMODEL];           // tf32-rounded
__device__ float g_xt[MTOT * DMODEL];            // tf32-rounded x
__device__ float g_wt[4 * DD];                   // tf32-rounded wq,wk,wv,wo

__device__ __forceinline__ uint32_t f2tf(float x) {
    uint32_t u;
    asm("cvt.rna.tf32.f32 %0, %1;" : "=r"(u) : "f"(x));
    return u;
}
__device__ __forceinline__ float rtf(float x) { return __uint_as_float(f2tf(x)); }

__device__ __forceinline__ float ex2(float x) {
    float r;
    asm("ex2.approx.f32 %0, %1;" : "=f"(r) : "f"(x));
    return r;
}

__device__ __forceinline__ void mma8(float* c, const uint32_t* a, uint32_t b0, uint32_t b1) {
    asm volatile(
        "mma.sync.aligned.m16n8k8.row.col.f32.tf32.tf32.f32 "
        "{%0,%1,%2,%3}, {%4,%5,%6,%7}, {%8,%9}, {%0,%1,%2,%3};"
        : "+f"(c[0]), "+f"(c[1]), "+f"(c[2]), "+f"(c[3])
        : "r"(a[0]), "r"(a[1]), "r"(a[2]), "r"(a[3]), "r"(b0), "r"(b1));
}

__device__ __forceinline__ void cp16(void* dst, const void* src) {
    uint32_t d = (uint32_t)__cvta_generic_to_shared(dst);
    asm volatile("cp.async.cg.shared.global [%0], [%1], 16;" :: "r"(d), "l"(src));
}
__device__ __forceinline__ void cp_commit() { asm volatile("cp.async.commit_group;"); }
template <int N>
__device__ __forceinline__ void cp_wait() { asm volatile("cp.async.wait_group %0;" :: "n"(N)); }

// ---------------------------------------------------------------------------
// Pre-pass: round x and weights to tf32 once (float4 granularity).
// ---------------------------------------------------------------------------
__global__ __launch_bounds__(256) void cvt_kernel(
    const float* __restrict__ x,
    const float* __restrict__ wq, const float* __restrict__ wk,
    const float* __restrict__ wv, const float* __restrict__ wo)
{
    const int NX = MTOT * DMODEL / 4;
    const int NW = DD / 4;
    int i = blockIdx.x * 256 + threadIdx.x;
    const float4* src;
    float4* dst;
    if (i < NX) {
        src = (const float4*)x + i;
        dst = (float4*)g_xt + i;
    } else {
        int j = i - NX;
        if (j >= 4 * NW) return;
        int w = j / NW, o = j % NW;
        const float* ws = (w == 0) ? wq : (w == 1) ? wk : (w == 2) ? wv : wo;
        src = (const float4*)ws + o;
        dst = (float4*)g_wt + (size_t)w * NW + o;
    }
    float4 v = *src;
    v.x = rtf(v.x); v.y = rtf(v.y); v.z = rtf(v.z); v.w = rtf(v.w);
    *dst = v;
}

// ---------------------------------------------------------------------------
// GEMM: Y[m,n] = sum_k X[m,k] * W[k,n] + bias[n]; inputs pre-rounded tf32.
// MODE 0: X=g_xt; W=g_wt[z]; epilogue scatters (permuted/scaled/rounded) q/k/v.
// MODE 1: X=g_ctx; W=g_wt[3]; raw output + bias.
// Tile BM=128 BN=64 BK=32, 256 threads, cp.async double-buffered.
// ---------------------------------------------------------------------------
#define GEMM_SMEM ((2 * 128 * 36 + 2 * 32 * 68) * 4)

template <int MODE>
__global__ __launch_bounds__(256) void gemm_kernel(
    const float* __restrict__ Bias0, const float* __restrict__ Bias1,
    const float* __restrict__ Bias2, float* __restrict__ OutP)
{
    extern __shared__ float gsm[];
    float* As = gsm;                 // 2 x 128 x 36
    float* Bs = gsm + 2 * 128 * 36;  // 2 x 32 x 68

    const int tid = threadIdx.x;
    const int wid = tid >> 5, lane = tid & 31;
    const int g = lane >> 2, tg = lane & 3;
    const int wm = wid & 3, wn = wid >> 2;
    const int m0 = blockIdx.y * 128;
    const int n0 = blockIdx.x * 64;

    const float* X;
    const float* W;
    const float* Bias;
    if (MODE == 0) {
        X = g_xt;
        const int z = blockIdx.z;
        W = g_wt + (size_t)z * DD;
        Bias = (z == 0) ? Bias0 : (z == 1) ? Bias1 : Bias2;
    } else {
        X = g_ctx;
        W = g_wt + 3 * (size_t)DD;
        Bias = Bias0;
    }

    auto load_tile = [&](int kt, int buf) {
        const float* src = X + (size_t)m0 * DMODEL + kt * 32;
        float* Ad = As + buf * 128 * 36;
#pragma unroll
        for (int i = 0; i < 4; i++) {
            int lin = tid + i * 256;
            int r = lin >> 3, c = (lin & 7) * 4;
            cp16(&Ad[r * 36 + c], src + (size_t)r * DMODEL + c);
        }
        const float* wsrc = W + (size_t)kt * 32 * DMODEL + n0;
        float* Bd = Bs + buf * 32 * 68;
#pragma unroll
        for (int i = 0; i < 2; i++) {
            int lin = tid + i * 256;
            int r = lin >> 4, c = (lin & 15) * 4;
            cp16(&Bd[r * 68 + c], wsrc + (size_t)r * DMODEL + c);
        }
        cp_commit();
    };

    float acc[2][4][4];
#pragma unroll
    for (int mt = 0; mt < 2; mt++)
#pragma unroll
        for (int nt = 0; nt < 4; nt++)
#pragma unroll
            for (int i = 0; i < 4; i++) acc[mt][nt][i] = 0.f;

    const int NKT = DMODEL / 32;  // 24
    load_tile(0, 0);

    for (int kt = 0; kt < NKT; kt++) {
        if (kt + 1 < NKT) {
            load_tile(kt + 1, (kt + 1) & 1);
            cp_wait<1>();
        } else {
            cp_wait<0>();
        }
        __syncthreads();

        const uint32_t* Ac = (const uint32_t*)(As + (kt & 1) * 128 * 36);
        const uint32_t* Bc = (const uint32_t*)(Bs + (kt & 1) * 32 * 68);

#pragma unroll
        for (int ks = 0; ks < 4; ks++) {
            uint32_t a[2][4];
#pragma unroll
            for (int mt = 0; mt < 2; mt++) {
                int r = wm * 32 + mt * 16;
                a[mt][0] = Ac[(r + g) * 36 + ks * 8 + tg];
                a[mt][1] = Ac[(r + 8 + g) * 36 + ks * 8 + tg];
                a[mt][2] = Ac[(r + g) * 36 + ks * 8 + tg + 4];
                a[mt][3] = Ac[(r + 8 + g) * 36 + ks * 8 + tg + 4];
            }
#pragma unroll
            for (int nt = 0; nt < 4; nt++) {
                uint32_t b0 = Bc[(ks * 8 + tg) * 68 + wn * 32 + nt * 8 + g];
                uint32_t b1 = Bc[(ks * 8 + tg + 4) * 68 + wn * 32 + nt * 8 + g];
                mma8(acc[0][nt], a[0], b0, b1);
                mma8(acc[1][nt], a[1], b0, b1);
            }
        }
        __syncthreads();
    }

    // epilogue
#pragma unroll
    for (int mt = 0; mt < 2; mt++) {
#pragma unroll
        for (int nt = 0; nt < 4; nt++) {
            int row = m0 + wm * 32 + mt * 16 + g;
            int col = n0 + wn * 32 + nt * 8 + 2 * tg;
            float bv0 = Bias[col], bv1 = Bias[col + 1];
            float x00 = acc[mt][nt][0] + bv0, x01 = acc[mt][nt][1] + bv1;
            float x10 = acc[mt][nt][2] + bv0, x11 = acc[mt][nt][3] + bv1;
            if (MODE == 0) {
                const int z = blockIdx.z;
                if (z == 0) { x00 *= QSCALE; x01 *= QSCALE; x10 *= QSCALE; x11 *= QSCALE; }
                x00 = rtf(x00); x01 = rtf(x01); x10 = rtf(x10); x11 = rtf(x11);
                int bb = row >> 12, s = row & 4095;
                int h = col >> 6, d = col & 63;
                if (z == 2) {
                    // V: [bh][d][s'] transposed, key-permuted
                    size_t bvp = (size_t)(bb * NHEADS + h) * DKH;
                    int sp = (s & ~7) | PI8(s & 7);
                    g_v[(bvp + d) * SEQ + sp]         = x00;
                    g_v[(bvp + d + 1) * SEQ + sp]     = x01;
                    g_v[(bvp + d) * SEQ + sp + 8]     = x10;
                    g_v[(bvp + d + 1) * SEQ + sp + 8] = x11;
                } else {
                    float* dst = (z == 0) ? g_q : g_k;
                    int dp = (d & ~7) | PI8(d & 7);  // logical even col -> phys; +1 -> phys+2
                    size_t base0 = ((size_t)(bb * NHEADS + h) * SEQ + s) * DKH;
                    size_t base1 = base0 + 8 * DKH;
                    dst[base0 + dp]     = x00;
                    dst[base0 + dp + 2] = x01;
                    dst[base1 + dp]     = x10;
                    dst[base1 + dp + 2] = x11;
                }
            } else {
                *(float2*)&OutP[(size_t)row * DMODEL + col] = make_float2(x00, x01);
                *(float2*)&OutP[(size_t)(row + 8) * DMODEL + col] = make_float2(x10, x11);
            }
        }
    }
}

// ---------------------------------------------------------------------------
// Flash attention: 128 threads (4 warps x 32 q-rows), 128-row q tile, 2 CTA/SM.
// K/V cp.async double-buffered; operands pre-rounded tf32; LDS.64 fragment
// pairs via the PI8 permute; exp2-domain online softmax (scores prescaled).
// ---------------------------------------------------------------------------
#define ATT_SMEM ((128 * 68 + 4 * 64 * 68) * 4)

__global__ __launch_bounds__(128, 2) void attn_kernel() {
    extern __shared__ float sm[];
    float* Qs = sm;                  // 128 x 68 : Q staging, then P staging
    float* Kb = sm + 128 * 68;       // 2 x 64 x 68 (rows=key, cols=d-permuted)
    float* Vb = Kb + 2 * 64 * 68;    // 2 x 64 x 68 (rows=d, cols=key-permuted)
    uint32_t* Ps = (uint32_t*)Qs;
    const uint32_t* Qu = (const uint32_t*)Qs;

    const int tid = threadIdx.x;
    const int wid = tid >> 5, lane = tid & 31;
    const int g = lane >> 2, tg = lane & 3;
    const int wb = wid * 32;
    const int bh = blockIdx.y;
    const int q0 = blockIdx.x * 128;

    const float* Qg = g_q + (size_t)bh * SEQ * DKH;
    const float* Kg = g_k + (size_t)bh * SEQ * DKH;
    const float* Vg = g_v + (size_t)bh * DKH * SEQ;

    // stage Q tile (128 x 64, already tf32 + prescaled + d-permuted)
#pragma unroll
    for (int i = 0; i < 16; i++) {
        int lin = tid + i * 128;
        int r = lin >> 4, c = (lin & 15) * 4;
        *(float4*)&Qs[r * 68 + c] = *(const float4*)(Qg + (size_t)(q0 + r) * DKH + c);
    }
    __syncthreads();

    // Q A-fragments via paired loads (warp-private rows)
    uint32_t qa[2][8][4];
#pragma unroll
    for (int mt = 0; mt < 2; mt++) {
        int r = wb + mt * 16;
#pragma unroll
        for (int ks = 0; ks < 8; ks++) {
            uint2 t0 = *(const uint2*)&Qu[(r + g) * 68 + ks * 8 + 2 * tg];
            uint2 t1 = *(const uint2*)&Qu[(r + 8 + g) * 68 + ks * 8 + 2 * tg];
            qa[mt][ks][0] = t0.x; qa[mt][ks][2] = t0.y;
            qa[mt][ks][1] = t1.x; qa[mt][ks][3] = t1.y;
        }
    }

    float o[2][8][4];
#pragma unroll
    for (int mt = 0; mt < 2; mt++)
#pragma unroll
        for (int nt = 0; nt < 8; nt++)
#pragma unroll
            for (int i = 0; i < 4; i++) o[mt][nt][i] = 0.f;
    float mrow[2][2] = {{-1e30f, -1e30f}, {-1e30f, -1e30f}};
    float lrow[2][2] = {{0.f, 0.f}, {0.f, 0.f}};

    auto load_kv = [&](int kt, int buf) {
        float* Kd = Kb + buf * 64 * 68;
        float* Vd = Vb + buf * 64 * 68;
#pragma unroll
        for (int i = 0; i < 8; i++) {
            int lin = tid + i * 128;
            int r = lin >> 4, c = (lin & 15) * 4;
            cp16(&Kd[r * 68 + c], Kg + (size_t)(kt * 64 + r) * DKH + c);
            cp16(&Vd[r * 68 + c], Vg + (size_t)r * SEQ + kt * 64 + c);
        }
        cp_commit();
    };

    load_kv(0, 0);

    for (int kt = 0; kt < SEQ / 64; kt++) {
        if (kt + 1 < SEQ / 64) {
            load_kv(kt + 1, (kt + 1) & 1);
            cp_wait<1>();
        } else {
            cp_wait<0>();
        }
        __syncthreads();

        const uint32_t* Ku = (const uint32_t*)(Kb + (kt & 1) * 64 * 68);
        const uint32_t* Vu = (const uint32_t*)(Vb + (kt & 1) * 64 * 68);

        // S = Q K^T (scores already in log2 domain via Q prescale)
        float sc[2][8][4];
#pragma unroll
        for (int mt = 0; mt < 2; mt++)
#pragma unroll
            for (int nt = 0; nt < 8; nt++)
#pragma unroll
                for (int i = 0; i < 4; i++) sc[mt][nt][i] = 0.f;
#pragma unroll
        for (int nt = 0; nt < 8; nt++) {
#pragma unroll
            for (int ks = 0; ks < 8; ks++) {
                uint2 bv = *(const uint2*)&Ku[(nt * 8 + g) * 68 + ks * 8 + 2 * tg];
                mma8(sc[0][nt], qa[0][ks], bv.x, bv.y);
                mma8(sc[1][nt], qa[1][ks], bv.x, bv.y);
            }
        }

        // online softmax (exp2 domain)
#pragma unroll
        for (int mt = 0; mt < 2; mt++) {
            float mx0 = -1e30f, mx1 = -1e30f;
#pragma unroll
            for (int nt = 0; nt < 8; nt++) {
                mx0 = fmaxf(mx0, fmaxf(sc[mt][nt][0], sc[mt][nt][1]));
                mx1 = fmaxf(mx1, fmaxf(sc[mt][nt][2], sc[mt][nt][3]));
            }
            mx0 = fmaxf(mx0, __shfl_xor_sync(0xffffffffu, mx0, 1));
            mx0 = fmaxf(mx0, __shfl_xor_sync(0xffffffffu, mx0, 2));
            mx1 = fmaxf(mx1, __shfl_xor_sync(0xffffffffu, mx1, 1));
            mx1 = fmaxf(mx1, __shfl_xor_sync(0xffffffffu, mx1, 2));
            float mn0 = fmaxf(mrow[mt][0], mx0), mn1 = fmaxf(mrow[mt][1], mx1);
            float al0 = ex2(mrow[mt][0] - mn0), al1 = ex2(mrow[mt][1] - mn1);
            mrow[mt][0] = mn0;
            mrow[mt][1] = mn1;

            int r = wb + mt * 16;
            float rs0 = 0.f, rs1 = 0.f;
#pragma unroll
            for (int nt = 0; nt < 8; nt++) {
                float p00 = ex2(sc[mt][nt][0] - mn0);
                float p01 = ex2(sc[mt][nt][1] - mn0);
                float p10 = ex2(sc[mt][nt][2] - mn1);
                float p11 = ex2(sc[mt][nt][3] - mn1);
                rs0 += p00 + p01;
                rs1 += p10 + p11;
                // store logical cols (2tg, 2tg+1) at phys (cb, cb+2)
                int cb = nt * 8 + ((tg & 1) * 4 + (tg >> 1));
                Ps[(r + g) * 68 + cb]         = f2tf(p00);
                Ps[(r + g) * 68 + cb + 2]     = f2tf(p01);
                Ps[(r + 8 + g) * 68 + cb]     = f2tf(p10);
                Ps[(r + 8 + g) * 68 + cb + 2] = f2tf(p11);
            }
            rs0 += __shfl_xor_sync(0xffffffffu, rs0, 1);
            rs0 += __shfl_xor_sync(0xffffffffu, rs0, 2);
            rs1 += __shfl_xor_sync(0xffffffffu, rs1, 1);
            rs1 += __shfl_xor_sync(0xffffffffu, rs1, 2);
            lrow[mt][0] = lrow[mt][0] * al0 + rs0;
            lrow[mt][1] = lrow[mt][1] * al1 + rs1;

#pragma unroll
            for (int nt = 0; nt < 8; nt++) {
                o[mt][nt][0] *= al0;
                o[mt][nt][1] *= al0;
                o[mt][nt][2] *= al1;
                o[mt][nt][3] *= al1;
            }
        }
        __syncwarp();  // P writes -> P reads (warp-private rows)

        // O += P V
#pragma unroll
        for (int ks = 0; ks < 8; ks++) {
            uint2 a00 = *(const uint2*)&Ps[(wb + g) * 68 + ks * 8 + 2 * tg];
            uint2 a01 = *(const uint2*)&Ps[(wb + 8 + g) * 68 + ks * 8 + 2 * tg];
            uint2 a10 = *(const uint2*)&Ps[(wb + 16 + g) * 68 + ks * 8 + 2 * tg];
            uint2 a11 = *(const uint2*)&Ps[(wb + 24 + g) * 68 + ks * 8 + 2 * tg];
            uint32_t pa0[4] = {a00.x, a01.x, a00.y, a01.y};
            uint32_t pa1[4] = {a10.x, a11.x, a10.y, a11.y};
#pragma unroll
            for (int nt = 0; nt < 8; nt++) {
                uint2 bv = *(const uint2*)&Vu[(nt * 8 + g) * 68 + ks * 8 + 2 * tg];
                mma8(o[0][nt], pa0, bv.x, bv.y);
                mma8(o[1][nt], pa1, bv.x, bv.y);
            }
        }
        __syncthreads();  // before next iter overwrites this K/V buffer
    }

    // finalize, write ctx [B,S,D] tf32-rounded (feeds out-proj GEMM directly)
    const int bb = bh / NHEADS, h = bh % NHEADS;
#pragma unroll
    for (int mt = 0; mt < 2; mt++) {
        const float inv0 = 1.f / lrow[mt][0], inv1 = 1.f / lrow[mt][1];
        const int s0 = q0 + wb + mt * 16 + g;
#pragma unroll
        for (int nt = 0; nt < 8; nt++) {
            int col = h * DKH + nt * 8 + 2 * tg;
            *(float2*)&g_ctx[((size_t)(bb * SEQ + s0)) * DMODEL + col] =
                make_float2(rtf(o[mt][nt][0] * inv0), rtf(o[mt][nt][1] * inv0));
            *(float2*)&g_ctx[((size_t)(bb * SEQ + s0 + 8)) * DMODEL + col] =
                make_float2(rtf(o[mt][nt][2] * inv1), rtf(o[mt][nt][3] * inv1));
        }
    }
}

// ---------------------------------------------------------------------------
extern "C" void kernel_launch(void* const* d_in, const int* in_sizes, int n_in,
                              void* d_out, int out_size) {
    const float* x  = (const float*)d_in[0];
    const float* wq = (const float*)d_in[1];
    const float* bq = (const float*)d_in[2];
    const float* wk = (const float*)d_in[3];
    const float* bk = (const float*)d_in[4];
    const float* wv = (const float*)d_in[5];
    const float* bv = (const float*)d_in[6];
    const float* wo = (const float*)d_in[7];
    const float* bo = (const float*)d_in[8];
    float* out = (float*)d_out;

    static bool attr_done = false;
    if (!attr_done) {
        cudaFuncSetAttribute(gemm_kernel<0>, cudaFuncAttributeMaxDynamicSharedMemorySize, GEMM_SMEM);
        cudaFuncSetAttribute(gemm_kernel<1>, cudaFuncAttributeMaxDynamicSharedMemorySize, GEMM_SMEM);
        cudaFuncSetAttribute(attn_kernel, cudaFuncAttributeMaxDynamicSharedMemorySize, ATT_SMEM);
        attr_done = true;
    }

    // 0) tf32 pre-round of x and weights
    {
        const int NX = MTOT * DMODEL / 4;
        const int NW = DD / 4;
        int total = NX + 4 * NW;
        cvt_kernel<<<(total + 255) / 256, 256>>>(x, wq, wk, wv, wo);
    }

    // 1) fused QKV projection -> permuted/scaled tf32 q/k/v
    gemm_kernel<0><<<dim3(DMODEL / 64, MTOT / 128, 3), 256, GEMM_SMEM>>>(bq, bk, bv, nullptr);

    // 2) flash attention -> g_ctx
    attn_kernel<<<dim3(SEQ / 128, NB * NHEADS), 128, ATT_SMEM>>>();

    // 3) output projection -> d_out
    gemm_kernel<1><<<dim3(DMODEL / 64, MTOT / 128, 1), 256, GEMM_SMEM>>>(bo, nullptr, nullptr, out);
}

// round 4
// speedup vs baseline: 1.2906x; 1.2906x over previous
#include <cuda_runtime.h>
#include <cstdint>

// Problem constants
#define DMODEL 768
#define NHEADS 12
#define DKH    64
#define NB     2
#define SEQ    4096
#define MTOT   (NB * SEQ)   // 8192
#define DD     (DMODEL * DMODEL)

// within-8 interleave: logical j -> physical, so that (j, j+4) land adjacent
#define PI8(j) (((j) < 4) ? (2 * (j)) : (2 * ((j) - 4) + 1))

#define QSCALE (0.125f * 1.4426950408889634f)  // 1/sqrt(dk) * log2(e)

// Scratch (device globals: allocation-free contract)
__device__ float g_q[NB * NHEADS * SEQ * DKH];   // [bh][s][d'] d-permuted, tf32, prescaled
__device__ float g_k[NB * NHEADS * SEQ * DKH];   // [bh][s][d'] d-permuted, tf32
__device__ float g_v[NB * NHEADS * DKH * SEQ];   // [bh][d][s] transposed (plain), tf32
__device__ float g_ctx[MTOT * DMODEL];           // tf32, k'-permuted cols
__device__ float g_xt[MTOT * DMODEL];            // tf32, k'-permuted
__device__ float g_wt[4 * DD];                   // W^T [n][k'], tf32, k'-permuted

__device__ __forceinline__ uint32_t f2tf(float x) {
    uint32_t u;
    asm("cvt.rna.tf32.f32 %0, %1;" : "=r"(u) : "f"(x));
    return u;
}
__device__ __forceinline__ float rtf(float x) { return __uint_as_float(f2tf(x)); }

__device__ __forceinline__ float ex2(float x) {
    float r;
    asm("ex2.approx.f32 %0, %1;" : "=f"(r) : "f"(x));
    return r;
}

__device__ __forceinline__ void mma8(float* c, const uint32_t* a, uint32_t b0, uint32_t b1) {
    asm volatile(
        "mma.sync.aligned.m16n8k8.row.col.f32.tf32.tf32.f32 "
        "{%0,%1,%2,%3}, {%4,%5,%6,%7}, {%8,%9}, {%0,%1,%2,%3};"
        : "+f"(c[0]), "+f"(c[1]), "+f"(c[2]), "+f"(c[3])
        : "r"(a[0]), "r"(a[1]), "r"(a[2]), "r"(a[3]), "r"(b0), "r"(b1));
}

__device__ __forceinline__ void cp16(void* dst, const void* src) {
    uint32_t d = (uint32_t)__cvta_generic_to_shared(dst);
    asm volatile("cp.async.cg.shared.global [%0], [%1], 16;" :: "r"(d), "l"(src));
}
__device__ __forceinline__ void cp_commit() { asm volatile("cp.async.commit_group;"); }
template <int N>
__device__ __forceinline__ void cp_wait() { asm volatile("cp.async.wait_group %0;" :: "n"(N)); }

// ---------------------------------------------------------------------------
// Pre-pass: tf32-round; x -> g_xt (k'-permuted); W -> g_wt transposed [n][k'].
// ---------------------------------------------------------------------------
__global__ __launch_bounds__(256) void cvt_kernel(
    const float* __restrict__ x,
    const float* __restrict__ wq, const float* __restrict__ wk,
    const float* __restrict__ wv, const float* __restrict__ wo)
{
    const int NX8 = MTOT * DMODEL / 8;        // x handled 8 floats/thread
    const int NWT = DMODEL * (DMODEL / 4);    // per-weight: (n, k-quad) pairs
    long i = (long)blockIdx.x * 256 + threadIdx.x;
    if (i < NX8) {
        const float4* s = (const float4*)x + i * 2;
        float4 v0 = s[0], v1 = s[1];
        // phys order within 8 = logical {0,4,1,5,2,6,3,7}
        float4 o0 = make_float4(rtf(v0.x), rtf(v1.x), rtf(v0.y), rtf(v1.y));
        float4 o1 = make_float4(rtf(v0.z), rtf(v1.z), rtf(v0.w), rtf(v1.w));
        float4* d = (float4*)g_xt + i * 2;
        d[0] = o0;
        d[1] = o1;
        return;
    }
    long j = i - NX8;
    if (j >= 4L * NWT) return;
    int w  = (int)(j / NWT);
    int t  = (int)(j % NWT);
    int n  = t / (DMODEL / 4);   // output row (n-dim)
    int kq = t % (DMODEL / 4);   // phys k quad
    const float* ws = (w == 0) ? wq : (w == 1) ? wk : (w == 2) ? wv : wo;
    float4 o;
    float* op = (float*)&o;
#pragma unroll
    for (int p4 = 0; p4 < 4; p4++) {
        int p  = kq * 4 + p4;
        int pl = p & 7, pb = p & ~7;
        int l  = (pl & 1) ? ((pl >> 1) + 4) : (pl >> 1);  // inverse PI8
        op[p4] = rtf(ws[(size_t)(pb + l) * DMODEL + n]);
    }
    *(float4*)(g_wt + (size_t)w * DD + (size_t)n * DMODEL + kq * 4) = o;
}

// ---------------------------------------------------------------------------
// GEMM: Y[m,n] = sum_k X[m,k'] * W^T[n,k'] + bias[n]. BM=128 BN=128 BK=32,
// 256 threads (8 warps, warp tile 32m x 64n), 4-stage cp.async, LDS.64 frags.
// MODE 0: X=g_xt, W=g_wt[z]; epilogue scatters q/k (d-permuted) / v ([d][s]).
// MODE 1: X=g_ctx, W=g_wt[3]; plain output + bias.
// ---------------------------------------------------------------------------
#define GSTG (2 * 128 * 40)                 // floats per stage (A tile + B tile)
#define GEMM_SMEM (4 * GSTG * 4)            // 163840 B

template <int MODE>
__global__ __launch_bounds__(256) void gemm_kernel(
    const float* __restrict__ Bias0, const float* __restrict__ Bias1,
    const float* __restrict__ Bias2, float* __restrict__ OutP)
{
    extern __shared__ float gsm[];
    const int tid = threadIdx.x;
    const int wid = tid >> 5, lane = tid & 31;
    const int g = lane >> 2, tg = lane & 3;
    const int wm = wid & 3, wn = wid >> 2;
    const int m0 = blockIdx.y * 128;
    const int n0 = blockIdx.x * 128;

    const float* X;
    const float* W;
    const float* Bias;
    if (MODE == 0) {
        X = g_xt;
        const int z = blockIdx.z;
        W = g_wt + (size_t)z * DD;
        Bias = (z == 0) ? Bias0 : (z == 1) ? Bias1 : Bias2;
    } else {
        X = g_ctx;
        W = g_wt + 3 * (size_t)DD;
        Bias = Bias0;
    }

    auto load_tile = [&](int kt, int st) {
        float* Ad = gsm + st * GSTG;
        float* Bd = Ad + 128 * 40;
        const float* xs = X + (size_t)m0 * DMODEL + kt * 32;
        const float* wsrc = W + (size_t)n0 * DMODEL + kt * 32;
#pragma unroll
        for (int i = 0; i < 4; i++) {
            int lin = tid + i * 256;
            int r = lin >> 3, c = (lin & 7) * 4;
            cp16(&Ad[r * 40 + c], xs + (size_t)r * DMODEL + c);
        }
#pragma unroll
        for (int i = 0; i < 4; i++) {
            int lin = tid + i * 256;
            int r = lin >> 3, c = (lin & 7) * 4;
            cp16(&Bd[r * 40 + c], wsrc + (size_t)r * DMODEL + c);
        }
        cp_commit();
    };

    float acc[2][8][4];
#pragma unroll
    for (int mt = 0; mt < 2; mt++)
#pragma unroll
        for (int nt = 0; nt < 8; nt++)
#pragma unroll
            for (int i = 0; i < 4; i++) acc[mt][nt][i] = 0.f;

    const int NKT = DMODEL / 32;  // 24
    load_tile(0, 0);
    load_tile(1, 1);

    for (int kt = 0; kt < NKT; kt++) {
        if (kt + 2 < NKT) load_tile(kt + 2, (kt + 2) & 3);
        else cp_commit();
        cp_wait<2>();
        __syncthreads();

        const uint32_t* Ac = (const uint32_t*)(gsm + (kt & 3) * GSTG);
        const uint32_t* Bc = Ac + 128 * 40;

#pragma unroll
        for (int ks = 0; ks < 4; ks++) {
            uint32_t a[2][4];
#pragma unroll
            for (int mt = 0; mt < 2; mt++) {
                int r = wm * 32 + mt * 16;
                uint2 t0 = *(const uint2*)&Ac[(r + g) * 40 + ks * 8 + 2 * tg];
                uint2 t1 = *(const uint2*)&Ac[(r + 8 + g) * 40 + ks * 8 + 2 * tg];
                a[mt][0] = t0.x; a[mt][1] = t1.x; a[mt][2] = t0.y; a[mt][3] = t1.y;
            }
#pragma unroll
            for (int nt = 0; nt < 8; nt++) {
                uint2 bv = *(const uint2*)&Bc[(wn * 64 + nt * 8 + g) * 40 + ks * 8 + 2 * tg];
                mma8(acc[0][nt], a[0], bv.x, bv.y);
                mma8(acc[1][nt], a[1], bv.x, bv.y);
            }
        }
    }

    // epilogue
#pragma unroll
    for (int mt = 0; mt < 2; mt++) {
#pragma unroll
        for (int nt = 0; nt < 8; nt++) {
            int row = m0 + wm * 32 + mt * 16 + g;
            int col = n0 + wn * 64 + nt * 8 + 2 * tg;
            float bv0 = Bias[col], bv1 = Bias[col + 1];
            float x00 = acc[mt][nt][0] + bv0, x01 = acc[mt][nt][1] + bv1;
            float x10 = acc[mt][nt][2] + bv0, x11 = acc[mt][nt][3] + bv1;
            if (MODE == 0) {
                const int z = blockIdx.z;
                if (z == 0) { x00 *= QSCALE; x01 *= QSCALE; x10 *= QSCALE; x11 *= QSCALE; }
                x00 = rtf(x00); x01 = rtf(x01); x10 = rtf(x10); x11 = rtf(x11);
                int bb = row >> 12, s = row & 4095;
                int h = col >> 6, d = col & 63;
                if (z == 2) {
                    // V: [bh][d][s] transposed, plain
                    size_t bvp = (size_t)(bb * NHEADS + h) * DKH;
                    g_v[(bvp + d) * SEQ + s]         = x00;
                    g_v[(bvp + d + 1) * SEQ + s]     = x01;
                    g_v[(bvp + d) * SEQ + s + 8]     = x10;
                    g_v[(bvp + d + 1) * SEQ + s + 8] = x11;
                } else {
                    float* dst = (z == 0) ? g_q : g_k;
                    int dp = (d & ~7) | PI8(d & 7);  // even logical -> phys; +1 -> phys+2
                    size_t base0 = ((size_t)(bb * NHEADS + h) * SEQ + s) * DKH;
                    size_t base1 = base0 + 8 * DKH;
                    dst[base0 + dp]     = x00;
                    dst[base0 + dp + 2] = x01;
                    dst[base1 + dp]     = x10;
                    dst[base1 + dp + 2] = x11;
                }
            } else {
                *(float2*)&OutP[(size_t)row * DMODEL + col] = make_float2(x00, x01);
                *(float2*)&OutP[(size_t)(row + 8) * DMODEL + col] = make_float2(x10, x11);
            }
        }
    }
}

// ---------------------------------------------------------------------------
// Flash attention: 256-row q tile, 8 warps x 32 rows (2 m-subtiles).
// Q frags straight from GMEM; K frags LDS.64 (d-permuted); V plain [d][s] so
// the S C-fragment IS the P A-fragment (k-slot -> key bijection PI8);
// 4-stage cp.async K/V pipeline; exp2-domain online softmax interleaved
// with PV mma. No P smem, no syncwarp.
// ---------------------------------------------------------------------------
#define ASTG (2 * 64 * 72)                  // floats per stage (K tile + V tile)
#define ATT_SMEM (4 * ASTG * 4)             // 147456 B

__global__ __launch_bounds__(256, 1) void attn_kernel() {
    extern __shared__ float sm[];

    const int tid = threadIdx.x;
    const int wid = tid >> 5, lane = tid & 31;
    const int g = lane >> 2, tg = lane & 3;
    const int bh = blockIdx.y;
    const int q0 = blockIdx.x * 256;

    const float* Kg = g_k + (size_t)bh * SEQ * DKH;
    const float* Vg = g_v + (size_t)bh * DKH * SEQ;

    // Q A-fragments straight from gmem (layout already d-permuted + prescaled)
    uint32_t qa[2][8][4];
    {
        const uint32_t* Qw = (const uint32_t*)(g_q + ((size_t)bh * SEQ + q0 + wid * 32) * DKH);
#pragma unroll
        for (int mt = 0; mt < 2; mt++) {
#pragma unroll
            for (int ks = 0; ks < 8; ks++) {
                uint2 t0 = *(const uint2*)&Qw[(mt * 16 + g) * DKH + ks * 8 + 2 * tg];
                uint2 t1 = *(const uint2*)&Qw[(mt * 16 + 8 + g) * DKH + ks * 8 + 2 * tg];
                qa[mt][ks][0] = t0.x; qa[mt][ks][1] = t1.x;
                qa[mt][ks][2] = t0.y; qa[mt][ks][3] = t1.y;
            }
        }
    }

    float o[2][8][4];
#pragma unroll
    for (int mt = 0; mt < 2; mt++)
#pragma unroll
        for (int nt = 0; nt < 8; nt++)
#pragma unroll
            for (int i = 0; i < 4; i++) o[mt][nt][i] = 0.f;
    float mrow[2][2] = {{-1e30f, -1e30f}, {-1e30f, -1e30f}};
    float lrow[2][2] = {{0.f, 0.f}, {0.f, 0.f}};

    auto load_kv = [&](int kt, int st) {
        float* Kd = sm + st * ASTG;
        float* Vd = Kd + 64 * 72;
#pragma unroll
        for (int i = 0; i < 4; i++) {
            int lin = tid + i * 256;
            int r = lin >> 4, c = (lin & 15) * 4;
            cp16(&Kd[r * 72 + c], Kg + (size_t)(kt * 64 + r) * DKH + c);
            cp16(&Vd[r * 72 + c], Vg + (size_t)r * SEQ + kt * 64 + c);
        }
        cp_commit();
    };

    const int NT = SEQ / 64;  // 64
    load_kv(0, 0);
    load_kv(1, 1);

    for (int kt = 0; kt < NT; kt++) {
        if (kt + 2 < NT) load_kv(kt + 2, (kt + 2) & 3);
        else cp_commit();
        cp_wait<2>();
        __syncthreads();

        const uint32_t* Ku = (const uint32_t*)(sm + (kt & 3) * ASTG);
        const uint32_t* Vu = Ku + 64 * 72;

        // S = Q K^T (log2 domain via Q prescale)
        float sc[2][8][4];
#pragma unroll
        for (int mt = 0; mt < 2; mt++)
#pragma unroll
            for (int nt = 0; nt < 8; nt++)
#pragma unroll
                for (int i = 0; i < 4; i++) sc[mt][nt][i] = 0.f;
#pragma unroll
        for (int nt = 0; nt < 8; nt++) {
#pragma unroll
            for (int ks = 0; ks < 8; ks++) {
                uint2 bv = *(const uint2*)&Ku[(nt * 8 + g) * 72 + ks * 8 + 2 * tg];
                mma8(sc[0][nt], qa[0][ks], bv.x, bv.y);
                mma8(sc[1][nt], qa[1][ks], bv.x, bv.y);
            }
        }

        // row max + rescale factors (per m-subtile; rows g / g+8)
        float mn[2][2], alv[2][2];
#pragma unroll
        for (int mt = 0; mt < 2; mt++) {
            float mx0 = -1e30f, mx1 = -1e30f;
#pragma unroll
            for (int nt = 0; nt < 8; nt++) {
                mx0 = fmaxf(mx0, fmaxf(sc[mt][nt][0], sc[mt][nt][1]));
                mx1 = fmaxf(mx1, fmaxf(sc[mt][nt][2], sc[mt][nt][3]));
            }
            mx0 = fmaxf(mx0, __shfl_xor_sync(0xffffffffu, mx0, 1));
            mx0 = fmaxf(mx0, __shfl_xor_sync(0xffffffffu, mx0, 2));
            mx1 = fmaxf(mx1, __shfl_xor_sync(0xffffffffu, mx1, 1));
            mx1 = fmaxf(mx1, __shfl_xor_sync(0xffffffffu, mx1, 2));
            mn[mt][0] = fmaxf(mrow[mt][0], mx0);
            mn[mt][1] = fmaxf(mrow[mt][1], mx1);
            alv[mt][0] = ex2(mrow[mt][0] - mn[mt][0]);
            alv[mt][1] = ex2(mrow[mt][1] - mn[mt][1]);
            mrow[mt][0] = mn[mt][0];
            mrow[mt][1] = mn[mt][1];
#pragma unroll
            for (int nt = 0; nt < 8; nt++) {
                o[mt][nt][0] *= alv[mt][0];
                o[mt][nt][1] *= alv[mt][0];
                o[mt][nt][2] *= alv[mt][1];
                o[mt][nt][3] *= alv[mt][1];
            }
        }

        // exp + PV, interleaved per score-group j (k-slot -> key = PI8 bijection)
        float rs[2][2] = {{0.f, 0.f}, {0.f, 0.f}};
#pragma unroll
        for (int j = 0; j < 8; j++) {
            uint32_t pa[2][4];
#pragma unroll
            for (int mt = 0; mt < 2; mt++) {
                float p00 = ex2(sc[mt][j][0] - mn[mt][0]);
                float p01 = ex2(sc[mt][j][1] - mn[mt][0]);
                float p10 = ex2(sc[mt][j][2] - mn[mt][1]);
                float p11 = ex2(sc[mt][j][3] - mn[mt][1]);
                rs[mt][0] += p00 + p01;
                rs[mt][1] += p10 + p11;
                pa[mt][0] = f2tf(p00);  // A-slot (g,    tg)   = P[g,   2tg]
                pa[mt][1] = f2tf(p10);  // A-slot (g+8,  tg)   = P[g+8, 2tg]
                pa[mt][2] = f2tf(p01);  // A-slot (g,    tg+4) = P[g,   2tg+1]
                pa[mt][3] = f2tf(p11);  // A-slot (g+8,  tg+4) = P[g+8, 2tg+1]
            }
#pragma unroll
            for (int nt = 0; nt < 8; nt++) {
                uint2 bv = *(const uint2*)&Vu[(nt * 8 + g) * 72 + j * 8 + 2 * tg];
                mma8(o[0][nt], pa[0], bv.x, bv.y);
                mma8(o[1][nt], pa[1], bv.x, bv.y);
            }
        }
#pragma unroll
        for (int mt = 0; mt < 2; mt++) {
            float r0 = rs[mt][0], r1 = rs[mt][1];
            r0 += __shfl_xor_sync(0xffffffffu, r0, 1);
            r0 += __shfl_xor_sync(0xffffffffu, r0, 2);
            r1 += __shfl_xor_sync(0xffffffffu, r1, 1);
            r1 += __shfl_xor_sync(0xffffffffu, r1, 2);
            lrow[mt][0] = lrow[mt][0] * alv[mt][0] + r0;
            lrow[mt][1] = lrow[mt][1] * alv[mt][1] + r1;
        }
    }

    // finalize: ctx [B,S,D] with k'-permuted cols (feeds out-proj), tf32
    const int bb = bh / NHEADS, h = bh % NHEADS;
    const int p0 = PI8(2 * tg), p1 = PI8(2 * tg + 1);
#pragma unroll
    for (int mt = 0; mt < 2; mt++) {
        const float inv0 = 1.f / lrow[mt][0], inv1 = 1.f / lrow[mt][1];
        const int s0 = q0 + wid * 32 + mt * 16 + g;
#pragma unroll
        for (int nt = 0; nt < 8; nt++) {
            int cb = h * 64 + nt * 8;
            float* r0p = &g_ctx[((size_t)(bb * SEQ + s0)) * DMODEL + cb];
            float* r1p = &g_ctx[((size_t)(bb * SEQ + s0 + 8)) * DMODEL + cb];
            r0p[p0] = rtf(o[mt][nt][0] * inv0);
            r0p[p1] = rtf(o[mt][nt][1] * inv0);
            r1p[p0] = rtf(o[mt][nt][2] * inv1);
            r1p[p1] = rtf(o[mt][nt][3] * inv1);
        }
    }
}

// ---------------------------------------------------------------------------
extern "C" void kernel_launch(void* const* d_in, const int* in_sizes, int n_in,
                              void* d_out, int out_size) {
    const float* x  = (const float*)d_in[0];
    const float* wq = (const float*)d_in[1];
    const float* bq = (const float*)d_in[2];
    const float* wk = (const float*)d_in[3];
    const float* bk = (const float*)d_in[4];
    const float* wv = (const float*)d_in[5];
    const float* bv = (const float*)d_in[6];
    const float* wo = (const float*)d_in[7];
    const float* bo = (const float*)d_in[8];
    float* out = (float*)d_out;

    static bool attr_done = false;
    if (!attr_done) {
        cudaFuncSetAttribute(gemm_kernel<0>, cudaFuncAttributeMaxDynamicSharedMemorySize, GEMM_SMEM);
        cudaFuncSetAttribute(gemm_kernel<1>, cudaFuncAttributeMaxDynamicSharedMemorySize, GEMM_SMEM);
        cudaFuncSetAttribute(attn_kernel, cudaFuncAttributeMaxDynamicSharedMemorySize, ATT_SMEM);
        attr_done = true;
    }

    // 0) tf32 pre-round + permute + weight transpose
    {
        const long NX8 = MTOT * DMODEL / 8;
        const long NWT = (long)DMODEL * (DMODEL / 4);
        long total = NX8 + 4 * NWT;
        cvt_kernel<<<(int)((total + 255) / 256), 256>>>(x, wq, wk, wv, wo);
    }

    // 1) fused QKV projection
    gemm_kernel<0><<<dim3(DMODEL / 128, MTOT / 128, 3), 256, GEMM_SMEM>>>(bq, bk, bv, nullptr);

    // 2) flash attention -> g_ctx
    attn_kernel<<<dim3(SEQ / 256, NB * NHEADS), 256, ATT_SMEM>>>();

    // 3) output projection -> d_out
    gemm_kernel<1><<<dim3(DMODEL / 128, MTOT / 128, 1), 256, GEMM_SMEM>>>(bo, nullptr, nullptr, out);
}

// round 5
// speedup vs baseline: 1.3194x; 1.0224x over previous
#include <cuda_runtime.h>
#include <cstdint>

// Problem constants
#define DMODEL 768
#define NHEADS 12
#define DKH    64
#define NB     2
#define SEQ    4096
#define MTOT   (NB * SEQ)   // 8192
#define DD     (DMODEL * DMODEL)

// within-8 interleave: logical j -> physical, so that (j, j+4) land adjacent
#define PI8(j) (((j) < 4) ? (2 * (j)) : (2 * ((j) - 4) + 1))

#define QSCALE (0.125f * 1.4426950408889634f)  // 1/sqrt(dk) * log2(e)

// Scratch (device globals: allocation-free contract)
__device__ float g_q[NB * NHEADS * SEQ * DKH];   // [bh][s][d'] d-permuted, tf32, prescaled
__device__ float g_k[NB * NHEADS * SEQ * DKH];   // [bh][s][d'] d-permuted, tf32
__device__ float g_v[NB * NHEADS * DKH * SEQ];   // [bh][d][s] transposed (plain), tf32
__device__ float g_ctx[MTOT * DMODEL];           // tf32, k'-permuted cols
__device__ float g_xt[MTOT * DMODEL];            // tf32, k'-permuted
__device__ float g_wt[4 * DD];                   // W^T [n][k'], tf32, k'-permuted

__device__ __forceinline__ uint32_t f2tf(float x) {
    uint32_t u;
    asm("cvt.rna.tf32.f32 %0, %1;" : "=r"(u) : "f"(x));
    return u;
}
__device__ __forceinline__ float rtf(float x) { return __uint_as_float(f2tf(x)); }

__device__ __forceinline__ float ex2(float x) {
    float r;
    asm("ex2.approx.f32 %0, %1;" : "=f"(r) : "f"(x));
    return r;
}

__device__ __forceinline__ void mma8(float* c, const uint32_t* a, uint32_t b0, uint32_t b1) {
    asm volatile(
        "mma.sync.aligned.m16n8k8.row.col.f32.tf32.tf32.f32 "
        "{%0,%1,%2,%3}, {%4,%5,%6,%7}, {%8,%9}, {%0,%1,%2,%3};"
        : "+f"(c[0]), "+f"(c[1]), "+f"(c[2]), "+f"(c[3])
        : "r"(a[0]), "r"(a[1]), "r"(a[2]), "r"(a[3]), "r"(b0), "r"(b1));
}

__device__ __forceinline__ void cp16(void* dst, const void* src) {
    uint32_t d = (uint32_t)__cvta_generic_to_shared(dst);
    asm volatile("cp.async.cg.shared.global [%0], [%1], 16;" :: "r"(d), "l"(src));
}
__device__ __forceinline__ void cp_commit() { asm volatile("cp.async.commit_group;"); }
template <int N>
__device__ __forceinline__ void cp_wait() { asm volatile("cp.async.wait_group %0;" :: "n"(N)); }

// ---------------------------------------------------------------------------
// Pre-pass: tf32-round; x -> g_xt (k'-permuted); W -> g_wt transposed [n][k'].
// ---------------------------------------------------------------------------
__global__ __launch_bounds__(256) void cvt_kernel(
    const float* __restrict__ x,
    const float* __restrict__ wq, const float* __restrict__ wk,
    const float* __restrict__ wv, const float* __restrict__ wo)
{
    const int NX8 = MTOT * DMODEL / 8;        // x handled 8 floats/thread
    const int NWT = DMODEL * (DMODEL / 4);    // per-weight: (n, k-quad) pairs
    long i = (long)blockIdx.x * 256 + threadIdx.x;
    if (i < NX8) {
        const float4* s = (const float4*)x + i * 2;
        float4 v0 = s[0], v1 = s[1];
        // phys order within 8 = logical {0,4,1,5,2,6,3,7}
        float4 o0 = make_float4(rtf(v0.x), rtf(v1.x), rtf(v0.y), rtf(v1.y));
        float4 o1 = make_float4(rtf(v0.z), rtf(v1.z), rtf(v0.w), rtf(v1.w));
        float4* d = (float4*)g_xt + i * 2;
        d[0] = o0;
        d[1] = o1;
        return;
    }
    long j = i - NX8;
    if (j >= 4L * NWT) return;
    int w  = (int)(j / NWT);
    int t  = (int)(j % NWT);
    int n  = t / (DMODEL / 4);   // output row (n-dim)
    int kq = t % (DMODEL / 4);   // phys k quad
    const float* ws = (w == 0) ? wq : (w == 1) ? wk : (w == 2) ? wv : wo;
    float4 o;
    float* op = (float*)&o;
#pragma unroll
    for (int p4 = 0; p4 < 4; p4++) {
        int p  = kq * 4 + p4;
        int pl = p & 7, pb = p & ~7;
        int l  = (pl & 1) ? ((pl >> 1) + 4) : (pl >> 1);  // inverse PI8
        op[p4] = rtf(ws[(size_t)(pb + l) * DMODEL + n]);
    }
    *(float4*)(g_wt + (size_t)w * DD + (size_t)n * DMODEL + kq * 4) = o;
}

// ---------------------------------------------------------------------------
// GEMM: Y[m,n] = sum_k X[m,k'] * W^T[n,k'] + bias[n]. BM=128 BN=128 BK=32,
// 256 threads (8 warps, warp tile 32m x 64n), 2-stage cp.async (80KB smem ->
// 2 CTAs/SM), LDS.64 frags.
// MODE 0: X=g_xt, W=g_wt[z]; epilogue scatters q/k (d-permuted) / v ([d][s]).
// MODE 1: X=g_ctx, W=g_wt[3]; plain output + bias.
// ---------------------------------------------------------------------------
#define GSTG (2 * 128 * 40)                 // floats per stage (A tile + B tile)
#define GEMM_SMEM (2 * GSTG * 4)            // 81920 B -> 2 CTAs/SM

template <int MODE>
__global__ __launch_bounds__(256, 2) void gemm_kernel(
    const float* __restrict__ Bias0, const float* __restrict__ Bias1,
    const float* __restrict__ Bias2, float* __restrict__ OutP)
{
    extern __shared__ float gsm[];
    const int tid = threadIdx.x;
    const int wid = tid >> 5, lane = tid & 31;
    const int g = lane >> 2, tg = lane & 3;
    const int wm = wid & 3, wn = wid >> 2;
    const int m0 = blockIdx.y * 128;
    const int n0 = blockIdx.x * 128;

    const float* X;
    const float* W;
    const float* Bias;
    if (MODE == 0) {
        X = g_xt;
        const int z = blockIdx.z;
        W = g_wt + (size_t)z * DD;
        Bias = (z == 0) ? Bias0 : (z == 1) ? Bias1 : Bias2;
    } else {
        X = g_ctx;
        W = g_wt + 3 * (size_t)DD;
        Bias = Bias0;
    }

    auto load_tile = [&](int kt, int st) {
        float* Ad = gsm + st * GSTG;
        float* Bd = Ad + 128 * 40;
        const float* xs = X + (size_t)m0 * DMODEL + kt * 32;
        const float* wsrc = W + (size_t)n0 * DMODEL + kt * 32;
#pragma unroll
        for (int i = 0; i < 4; i++) {
            int lin = tid + i * 256;
            int r = lin >> 3, c = (lin & 7) * 4;
            cp16(&Ad[r * 40 + c], xs + (size_t)r * DMODEL + c);
        }
#pragma unroll
        for (int i = 0; i < 4; i++) {
            int lin = tid + i * 256;
            int r = lin >> 3, c = (lin & 7) * 4;
            cp16(&Bd[r * 40 + c], wsrc + (size_t)r * DMODEL + c);
        }
        cp_commit();
    };

    float acc[2][8][4];
#pragma unroll
    for (int mt = 0; mt < 2; mt++)
#pragma unroll
        for (int nt = 0; nt < 8; nt++)
#pragma unroll
            for (int i = 0; i < 4; i++) acc[mt][nt][i] = 0.f;

    const int NKT = DMODEL / 32;  // 24
    load_tile(0, 0);

    for (int kt = 0; kt < NKT; kt++) {
        if (kt + 1 < NKT) {
            load_tile(kt + 1, (kt + 1) & 1);
            cp_wait<1>();
        } else {
            cp_wait<0>();
        }
        __syncthreads();

        const uint32_t* Ac = (const uint32_t*)(gsm + (kt & 1) * GSTG);
        const uint32_t* Bc = Ac + 128 * 40;

#pragma unroll
        for (int ks = 0; ks < 4; ks++) {
            uint32_t a[2][4];
#pragma unroll
            for (int mt = 0; mt < 2; mt++) {
                int r = wm * 32 + mt * 16;
                uint2 t0 = *(const uint2*)&Ac[(r + g) * 40 + ks * 8 + 2 * tg];
                uint2 t1 = *(const uint2*)&Ac[(r + 8 + g) * 40 + ks * 8 + 2 * tg];
                a[mt][0] = t0.x; a[mt][1] = t1.x; a[mt][2] = t0.y; a[mt][3] = t1.y;
            }
#pragma unroll
            for (int nt = 0; nt < 8; nt++) {
                uint2 bv = *(const uint2*)&Bc[(wn * 64 + nt * 8 + g) * 40 + ks * 8 + 2 * tg];
                mma8(acc[0][nt], a[0], bv.x, bv.y);
                mma8(acc[1][nt], a[1], bv.x, bv.y);
            }
        }
        __syncthreads();
    }

    // epilogue
#pragma unroll
    for (int mt = 0; mt < 2; mt++) {
#pragma unroll
        for (int nt = 0; nt < 8; nt++) {
            int row = m0 + wm * 32 + mt * 16 + g;
            int col = n0 + wn * 64 + nt * 8 + 2 * tg;
            float bv0 = Bias[col], bv1 = Bias[col + 1];
            float x00 = acc[mt][nt][0] + bv0, x01 = acc[mt][nt][1] + bv1;
            float x10 = acc[mt][nt][2] + bv0, x11 = acc[mt][nt][3] + bv1;
            if (MODE == 0) {
                const int z = blockIdx.z;
                if (z == 0) { x00 *= QSCALE; x01 *= QSCALE; x10 *= QSCALE; x11 *= QSCALE; }
                x00 = rtf(x00); x01 = rtf(x01); x10 = rtf(x10); x11 = rtf(x11);
                int bb = row >> 12, s = row & 4095;
                int h = col >> 6, d = col & 63;
                if (z == 2) {
                    // V: [bh][d][s] transposed, plain
                    size_t bvp = (size_t)(bb * NHEADS + h) * DKH;
                    g_v[(bvp + d) * SEQ + s]         = x00;
                    g_v[(bvp + d + 1) * SEQ + s]     = x01;
                    g_v[(bvp + d) * SEQ + s + 8]     = x10;
                    g_v[(bvp + d + 1) * SEQ + s + 8] = x11;
                } else {
                    float* dst = (z == 0) ? g_q : g_k;
                    int dp = (d & ~7) | PI8(d & 7);  // even logical -> phys; +1 -> phys+2
                    size_t base0 = ((size_t)(bb * NHEADS + h) * SEQ + s) * DKH;
                    size_t base1 = base0 + 8 * DKH;
                    dst[base0 + dp]     = x00;
                    dst[base0 + dp + 2] = x01;
                    dst[base1 + dp]     = x10;
                    dst[base1 + dp + 2] = x11;
                }
            } else {
                *(float2*)&OutP[(size_t)row * DMODEL + col] = make_float2(x00, x01);
                *(float2*)&OutP[(size_t)(row + 8) * DMODEL + col] = make_float2(x10, x11);
            }
        }
    }
}

// ---------------------------------------------------------------------------
// Flash attention: 128-row q tile, 4 warps x 32 rows (2 m-subtiles),
// 128 threads, 3-stage cp.async (110.6KB -> 2 CTAs/SM for cross-CTA overlap).
// Q frags straight from GMEM; V plain [d][s] so the S C-fragment IS the P
// A-fragment (k-slot -> key bijection PI8); exp2-domain online softmax.
// ---------------------------------------------------------------------------
#define ASTG (2 * 64 * 72)                  // floats per stage (K tile + V tile)
#define ATT_SMEM (3 * ASTG * 4)             // 110592 B

__global__ __launch_bounds__(128, 2) void attn_kernel() {
    extern __shared__ float sm[];

    const int tid = threadIdx.x;
    const int wid = tid >> 5, lane = tid & 31;
    const int g = lane >> 2, tg = lane & 3;
    const int bh = blockIdx.y;
    const int q0 = blockIdx.x * 128;

    const float* Kg = g_k + (size_t)bh * SEQ * DKH;
    const float* Vg = g_v + (size_t)bh * DKH * SEQ;

    // Q A-fragments straight from gmem (layout already d-permuted + prescaled)
    uint32_t qa[2][8][4];
    {
        const uint32_t* Qw = (const uint32_t*)(g_q + ((size_t)bh * SEQ + q0 + wid * 32) * DKH);
#pragma unroll
        for (int mt = 0; mt < 2; mt++) {
#pragma unroll
            for (int ks = 0; ks < 8; ks++) {
                uint2 t0 = *(const uint2*)&Qw[(mt * 16 + g) * DKH + ks * 8 + 2 * tg];
                uint2 t1 = *(const uint2*)&Qw[(mt * 16 + 8 + g) * DKH + ks * 8 + 2 * tg];
                qa[mt][ks][0] = t0.x; qa[mt][ks][1] = t1.x;
                qa[mt][ks][2] = t0.y; qa[mt][ks][3] = t1.y;
            }
        }
    }

    float o[2][8][4];
#pragma unroll
    for (int mt = 0; mt < 2; mt++)
#pragma unroll
        for (int nt = 0; nt < 8; nt++)
#pragma unroll
            for (int i = 0; i < 4; i++) o[mt][nt][i] = 0.f;
    float mrow[2][2] = {{-1e30f, -1e30f}, {-1e30f, -1e30f}};
    float lrow[2][2] = {{0.f, 0.f}, {0.f, 0.f}};

    auto load_kv = [&](int kt, int st) {
        float* Kd = sm + st * ASTG;
        float* Vd = Kd + 64 * 72;
#pragma unroll
        for (int i = 0; i < 8; i++) {
            int lin = tid + i * 128;
            int r = lin >> 4, c = (lin & 15) * 4;
            cp16(&Kd[r * 72 + c], Kg + (size_t)(kt * 64 + r) * DKH + c);
            cp16(&Vd[r * 72 + c], Vg + (size_t)r * SEQ + kt * 64 + c);
        }
        cp_commit();
    };

    const int NT = SEQ / 64;  // 64
    load_kv(0, 0);
    load_kv(1, 1);

    int cur = 0, nxt = 2;
    for (int kt = 0; kt < NT; kt++) {
        cp_wait<1>();
        __syncthreads();  // stage `cur` visible to all; stage `nxt` free (kt-1 done)
        if (kt + 2 < NT) load_kv(kt + 2, nxt);
        else cp_commit();

        const uint32_t* Ku = (const uint32_t*)(sm + cur * ASTG);
        const uint32_t* Vu = Ku + 64 * 72;
        cur = (cur == 2) ? 0 : cur + 1;
        nxt = (nxt == 2) ? 0 : nxt + 1;

        // S = Q K^T (log2 domain via Q prescale)
        float sc[2][8][4];
#pragma unroll
        for (int mt = 0; mt < 2; mt++)
#pragma unroll
            for (int nt = 0; nt < 8; nt++)
#pragma unroll
                for (int i = 0; i < 4; i++) sc[mt][nt][i] = 0.f;
#pragma unroll
        for (int nt = 0; nt < 8; nt++) {
#pragma unroll
            for (int ks = 0; ks < 8; ks++) {
                uint2 bv = *(const uint2*)&Ku[(nt * 8 + g) * 72 + ks * 8 + 2 * tg];
                mma8(sc[0][nt], qa[0][ks], bv.x, bv.y);
                mma8(sc[1][nt], qa[1][ks], bv.x, bv.y);
            }
        }

        // row max + rescale factors (per m-subtile; rows g / g+8)
        float mn[2][2], alv[2][2];
#pragma unroll
        for (int mt = 0; mt < 2; mt++) {
            float mx0 = -1e30f, mx1 = -1e30f;
#pragma unroll
            for (int nt = 0; nt < 8; nt++) {
                mx0 = fmaxf(mx0, fmaxf(sc[mt][nt][0], sc[mt][nt][1]));
                mx1 = fmaxf(mx1, fmaxf(sc[mt][nt][2], sc[mt][nt][3]));
            }
            mx0 = fmaxf(mx0, __shfl_xor_sync(0xffffffffu, mx0, 1));
            mx0 = fmaxf(mx0, __shfl_xor_sync(0xffffffffu, mx0, 2));
            mx1 = fmaxf(mx1, __shfl_xor_sync(0xffffffffu, mx1, 1));
            mx1 = fmaxf(mx1, __shfl_xor_sync(0xffffffffu, mx1, 2));
            mn[mt][0] = fmaxf(mrow[mt][0], mx0);
            mn[mt][1] = fmaxf(mrow[mt][1], mx1);
            alv[mt][0] = ex2(mrow[mt][0] - mn[mt][0]);
            alv[mt][1] = ex2(mrow[mt][1] - mn[mt][1]);
            mrow[mt][0] = mn[mt][0];
            mrow[mt][1] = mn[mt][1];
#pragma unroll
            for (int nt = 0; nt < 8; nt++) {
                o[mt][nt][0] *= alv[mt][0];
                o[mt][nt][1] *= alv[mt][0];
                o[mt][nt][2] *= alv[mt][1];
                o[mt][nt][3] *= alv[mt][1];
            }
        }

        // exp + PV, interleaved per score-group j (k-slot -> key = PI8 bijection)
        float rs[2][2] = {{0.f, 0.f}, {0.f, 0.f}};
#pragma unroll
        for (int j = 0; j < 8; j++) {
            uint32_t pa[2][4];
#pragma unroll
            for (int mt = 0; mt < 2; mt++) {
                float p00 = ex2(sc[mt][j][0] - mn[mt][0]);
                float p01 = ex2(sc[mt][j][1] - mn[mt][0]);
                float p10 = ex2(sc[mt][j][2] - mn[mt][1]);
                float p11 = ex2(sc[mt][j][3] - mn[mt][1]);
                rs[mt][0] += p00 + p01;
                rs[mt][1] += p10 + p11;
                pa[mt][0] = f2tf(p00);  // A-slot (g,   tg)   = P[g,   2tg]
                pa[mt][1] = f2tf(p10);  // A-slot (g+8, tg)   = P[g+8, 2tg]
                pa[mt][2] = f2tf(p01);  // A-slot (g,   tg+4) = P[g,   2tg+1]
                pa[mt][3] = f2tf(p11);  // A-slot (g+8, tg+4) = P[g+8, 2tg+1]
            }
#pragma unroll
            for (int nt = 0; nt < 8; nt++) {
                uint2 bv = *(const uint2*)&Vu[(nt * 8 + g) * 72 + j * 8 + 2 * tg];
                mma8(o[0][nt], pa[0], bv.x, bv.y);
                mma8(o[1][nt], pa[1], bv.x, bv.y);
            }
        }
#pragma unroll
        for (int mt = 0; mt < 2; mt++) {
            float r0 = rs[mt][0], r1 = rs[mt][1];
            r0 += __shfl_xor_sync(0xffffffffu, r0, 1);
            r0 += __shfl_xor_sync(0xffffffffu, r0, 2);
            r1 += __shfl_xor_sync(0xffffffffu, r1, 1);
            r1 += __shfl_xor_sync(0xffffffffu, r1, 2);
            lrow[mt][0] = lrow[mt][0] * alv[mt][0] + r0;
            lrow[mt][1] = lrow[mt][1] * alv[mt][1] + r1;
        }
    }

    // finalize: ctx [B,S,D] with k'-permuted cols (feeds out-proj), tf32
    const int bb = bh / NHEADS, h = bh % NHEADS;
    const int p0 = PI8(2 * tg), p1 = PI8(2 * tg + 1);
#pragma unroll
    for (int mt = 0; mt < 2; mt++) {
        const float inv0 = 1.f / lrow[mt][0], inv1 = 1.f / lrow[mt][1];
        const int s0 = q0 + wid * 32 + mt * 16 + g;
#pragma unroll
        for (int nt = 0; nt < 8; nt++) {
            int cb = h * 64 + nt * 8;
            float* r0p = &g_ctx[((size_t)(bb * SEQ + s0)) * DMODEL + cb];
            float* r1p = &g_ctx[((size_t)(bb * SEQ + s0 + 8)) * DMODEL + cb];
            r0p[p0] = rtf(o[mt][nt][0] * inv0);
            r0p[p1] = rtf(o[mt][nt][1] * inv0);
            r1p[p0] = rtf(o[mt][nt][2] * inv1);
            r1p[p1] = rtf(o[mt][nt][3] * inv1);
        }
    }
}

// ---------------------------------------------------------------------------
extern "C" void kernel_launch(void* const* d_in, const int* in_sizes, int n_in,
                              void* d_out, int out_size) {
    const float* x  = (const float*)d_in[0];
    const float* wq = (const float*)d_in[1];
    const float* bq = (const float*)d_in[2];
    const float* wk = (const float*)d_in[3];
    const float* bk = (const float*)d_in[4];
    const float* wv = (const float*)d_in[5];
    const float* bv = (const float*)d_in[6];
    const float* wo = (const float*)d_in[7];
    const float* bo = (const float*)d_in[8];
    float* out = (float*)d_out;

    static bool attr_done = false;
    if (!attr_done) {
        cudaFuncSetAttribute(gemm_kernel<0>, cudaFuncAttributeMaxDynamicSharedMemorySize, GEMM_SMEM);
        cudaFuncSetAttribute(gemm_kernel<1>, cudaFuncAttributeMaxDynamicSharedMemorySize, GEMM_SMEM);
        cudaFuncSetAttribute(attn_kernel, cudaFuncAttributeMaxDynamicSharedMemorySize, ATT_SMEM);
        attr_done = true;
    }

    // 0) tf32 pre-round + permute + weight transpose
    {
        const long NX8 = MTOT * DMODEL / 8;
        const long NWT = (long)DMODEL * (DMODEL / 4);
        long total = NX8 + 4 * NWT;
        cvt_kernel<<<(int)((total + 255) / 256), 256>>>(x, wq, wk, wv, wo);
    }

    // 1) fused QKV projection
    gemm_kernel<0><<<dim3(DMODEL / 128, MTOT / 128, 3), 256, GEMM_SMEM>>>(bq, bk, bv, nullptr);

    // 2) flash attention -> g_ctx
    attn_kernel<<<dim3(SEQ / 128, NB * NHEADS), 128, ATT_SMEM>>>();

    // 3) output projection -> d_out
    gemm_kernel<1><<<dim3(DMODEL / 128, MTOT / 128, 1), 256, GEMM_SMEM>>>(bo, nullptr, nullptr, out);
}

// round 6
// speedup vs baseline: 2.4321x; 1.8433x over previous
#include <cuda_runtime.h>
#include <cuda_fp16.h>
#include <cstdint>

// Problem constants
#define DMODEL 768
#define NHEADS 12
#define DKH    64
#define NB     2
#define SEQ    4096
#define MTOT   (NB * SEQ)   // 8192
#define DD     (DMODEL * DMODEL)

// within-8 interleave on 32-bit (half2) units: logical j -> physical,
// so that units (j, j+4) of a 16-half k-chunk land adjacent -> LDS.64 pairs
#define PI8(j) (((j) < 4) ? (2 * (j)) : (2 * ((j) - 4) + 1))

#define QSCALE (0.125f * 1.4426950408889634f)  // 1/sqrt(dk) * log2(e)

// Scratch (device globals: allocation-free contract) — all fp16 now
__device__ __half g_q[NB * NHEADS * SEQ * DKH];   // [bh][s][d] d-units PI8, prescaled
__device__ __half g_k[NB * NHEADS * SEQ * DKH];   // [bh][s][d] d-units PI8
__device__ __half g_v[NB * NHEADS * DKH * SEQ];   // [bh][d][s] transposed, s-units PI8
__device__ __half g_ctx[MTOT * DMODEL];           // [B,S,D] k-units PI8
__device__ __half g_xt[MTOT * DMODEL];            // k-units PI8
__device__ __half g_wt[4 * DD];                   // W^T [n][k] k-units PI8

__device__ __forceinline__ uint32_t pack2(float a, float b) {
    __half2 h = __floats2half2_rn(a, b);
    return *reinterpret_cast<uint32_t*>(&h);
}

__device__ __forceinline__ float ex2(float x) {
    float r;
    asm("ex2.approx.f32 %0, %1;" : "=f"(r) : "f"(x));
    return r;
}

// m16n8k16 fp16 mma, fp32 accum
__device__ __forceinline__ void mma16(float* c, const uint32_t* a, uint32_t b0, uint32_t b1) {
    asm volatile(
        "mma.sync.aligned.m16n8k16.row.col.f32.f16.f16.f32 "
        "{%0,%1,%2,%3}, {%4,%5,%6,%7}, {%8,%9}, {%0,%1,%2,%3};"
        : "+f"(c[0]), "+f"(c[1]), "+f"(c[2]), "+f"(c[3])
        : "r"(a[0]), "r"(a[1]), "r"(a[2]), "r"(a[3]), "r"(b0), "r"(b1));
}

__device__ __forceinline__ void cp16(void* dst, const void* src) {
    uint32_t d = (uint32_t)__cvta_generic_to_shared(dst);
    asm volatile("cp.async.cg.shared.global [%0], [%1], 16;" :: "r"(d), "l"(src));
}
__device__ __forceinline__ void cp_commit() { asm volatile("cp.async.commit_group;"); }
template <int N>
__device__ __forceinline__ void cp_wait() { asm volatile("cp.async.wait_group %0;" :: "n"(N)); }

// ---------------------------------------------------------------------------
// Pre-pass: fp32 -> fp16; x -> g_xt (k-unit PI8); W -> g_wt W^T[n][k] (k-unit PI8).
// ---------------------------------------------------------------------------
__global__ __launch_bounds__(256) void cvt_kernel(
    const float* __restrict__ x,
    const float* __restrict__ wq, const float* __restrict__ wk,
    const float* __restrict__ wv, const float* __restrict__ wo)
{
    const int NX16 = MTOT * DMODEL / 16;       // x: 16 floats / thread (one unit-group)
    const int NWT  = DMODEL * (DMODEL / 16);   // per weight: (n, 16-k group)
    long i = (long)blockIdx.x * 256 + threadIdx.x;
    if (i < NX16) {
        const float4* s = (const float4*)x + i * 4;
        float e[16];
#pragma unroll
        for (int q4 = 0; q4 < 4; q4++) {
            float4 v = s[q4];
            e[q4 * 4 + 0] = v.x; e[q4 * 4 + 1] = v.y;
            e[q4 * 4 + 2] = v.z; e[q4 * 4 + 3] = v.w;
        }
        uint32_t out[8];
#pragma unroll
        for (int l = 0; l < 8; l++) out[PI8(l)] = pack2(e[2 * l], e[2 * l + 1]);
        uint4* d = (uint4*)((uint32_t*)g_xt + i * 8);
        d[0] = make_uint4(out[0], out[1], out[2], out[3]);
        d[1] = make_uint4(out[4], out[5], out[6], out[7]);
        return;
    }
    long j = i - NX16;
    if (j >= 4L * NWT) return;
    int w = (int)(j / NWT);
    int t = (int)(j % NWT);
    int n = t / (DMODEL / 16);
    int G = t % (DMODEL / 16);   // 16-k group
    const float* ws = (w == 0) ? wq : (w == 1) ? wk : (w == 2) ? wv : wo;
    uint32_t out[8];
#pragma unroll
    for (int p = 0; p < 8; p++) {
        int l  = (p & 1) ? (p / 2 + 4) : (p / 2);  // inverse PI8
        int k0 = G * 16 + 2 * l;
        out[p] = pack2(ws[(size_t)k0 * DMODEL + n], ws[(size_t)(k0 + 1) * DMODEL + n]);
    }
    uint4* d = (uint4*)((uint32_t*)g_wt + ((size_t)w * DD + (size_t)n * DMODEL) / 2 + G * 8);
    d[0] = make_uint4(out[0], out[1], out[2], out[3]);
    d[1] = make_uint4(out[4], out[5], out[6], out[7]);
}

// ---------------------------------------------------------------------------
// GEMM: Y[m,n] = sum_k X[m,k] * W^T[n,k] + bias[n], fp16 in / fp32 acc.
// BM=128 BN=128 BK=64, 256 threads (8 warps, warp 32m x 64n), 2-stage
// cp.async (80KB -> 2 CTAs/SM), LDS.64 frags via PI8 units.
// MODE 0: X=g_xt, W=g_wt[z]; scatters q/k (half2 units) / v ([d][s] halves).
// MODE 1: X=g_ctx, W=g_wt[3]; fp32 output + bias.
// ---------------------------------------------------------------------------
#define GAS 80                                   // halves per smem row (40 words)
#define GSTG (2 * 128 * GAS)                     // halves per stage (A + B)
#define GEMM_SMEM (2 * GSTG * 2)                 // 81920 B

template <int MODE>
__global__ __launch_bounds__(256, 2) void gemm_kernel(
    const float* __restrict__ Bias0, const float* __restrict__ Bias1,
    const float* __restrict__ Bias2, float* __restrict__ OutP)
{
    extern __shared__ __half gsm[];
    const int tid = threadIdx.x;
    const int wid = tid >> 5, lane = tid & 31;
    const int g = lane >> 2, tg = lane & 3;
    const int wm = wid & 3, wn = wid >> 2;
    const int m0 = blockIdx.y * 128;
    const int n0 = blockIdx.x * 128;

    const __half* X;
    const __half* W;
    const float* Bias;
    if (MODE == 0) {
        X = g_xt;
        const int z = blockIdx.z;
        W = g_wt + (size_t)z * DD;
        Bias = (z == 0) ? Bias0 : (z == 1) ? Bias1 : Bias2;
    } else {
        X = g_ctx;
        W = g_wt + 3 * (size_t)DD;
        Bias = Bias0;
    }

    auto load_tile = [&](int kt, int st) {
        __half* Ad = gsm + st * GSTG;
        __half* Bd = Ad + 128 * GAS;
        const __half* xs = X + (size_t)m0 * DMODEL + kt * 64;
        const __half* wsrc = W + (size_t)n0 * DMODEL + kt * 64;
#pragma unroll
        for (int i = 0; i < 4; i++) {
            int lin = tid + i * 256;
            int r = lin >> 3, c = (lin & 7) * 8;
            cp16(&Ad[r * GAS + c], xs + (size_t)r * DMODEL + c);
        }
#pragma unroll
        for (int i = 0; i < 4; i++) {
            int lin = tid + i * 256;
            int r = lin >> 3, c = (lin & 7) * 8;
            cp16(&Bd[r * GAS + c], wsrc + (size_t)r * DMODEL + c);
        }
        cp_commit();
    };

    float acc[2][8][4];
#pragma unroll
    for (int mt = 0; mt < 2; mt++)
#pragma unroll
        for (int nt = 0; nt < 8; nt++)
#pragma unroll
            for (int i = 0; i < 4; i++) acc[mt][nt][i] = 0.f;

    const int NKT = DMODEL / 64;  // 12
    load_tile(0, 0);

    for (int kt = 0; kt < NKT; kt++) {
        if (kt + 1 < NKT) {
            load_tile(kt + 1, (kt + 1) & 1);
            cp_wait<1>();
        } else {
            cp_wait<0>();
        }
        __syncthreads();

        const uint32_t* Ac = (const uint32_t*)(gsm + (kt & 1) * GSTG);
        const uint32_t* Bc = Ac + 128 * (GAS / 2);

#pragma unroll
        for (int ks = 0; ks < 4; ks++) {
            uint32_t a[2][4];
#pragma unroll
            for (int mt = 0; mt < 2; mt++) {
                int r = wm * 32 + mt * 16;
                uint2 t0 = *(const uint2*)&Ac[(r + g) * 40 + ks * 8 + 2 * tg];
                uint2 t1 = *(const uint2*)&Ac[(r + 8 + g) * 40 + ks * 8 + 2 * tg];
                a[mt][0] = t0.x; a[mt][1] = t1.x; a[mt][2] = t0.y; a[mt][3] = t1.y;
            }
#pragma unroll
            for (int nt = 0; nt < 8; nt++) {
                uint2 bv = *(const uint2*)&Bc[(wn * 64 + nt * 8 + g) * 40 + ks * 8 + 2 * tg];
                mma16(acc[0][nt], a[0], bv.x, bv.y);
                mma16(acc[1][nt], a[1], bv.x, bv.y);
            }
        }
        __syncthreads();
    }

    // epilogue
#pragma unroll
    for (int mt = 0; mt < 2; mt++) {
#pragma unroll
        for (int nt = 0; nt < 8; nt++) {
            int row = m0 + wm * 32 + mt * 16 + g;
            int col = n0 + wn * 64 + nt * 8 + 2 * tg;   // even
            float bv0 = Bias[col], bv1 = Bias[col + 1];
            float x00 = acc[mt][nt][0] + bv0, x01 = acc[mt][nt][1] + bv1;
            float x10 = acc[mt][nt][2] + bv0, x11 = acc[mt][nt][3] + bv1;
            if (MODE == 0) {
                const int z = blockIdx.z;
                if (z == 0) { x00 *= QSCALE; x01 *= QSCALE; x10 *= QSCALE; x11 *= QSCALE; }
                int bb = row >> 12, s = row & 4095;
                int h = col >> 6, d = col & 63;
                if (z == 2) {
                    // V: [bh][d][s] halves, s-units PI8-permuted
                    size_t bvp = (size_t)(bb * NHEADS + h) * DKH;
                    int u0 = s >> 1, u1 = (s + 8) >> 1;
                    int ps0 = 2 * ((u0 & ~7) | PI8(u0 & 7)) + (s & 1);
                    int ps1 = 2 * ((u1 & ~7) | PI8(u1 & 7)) + (s & 1);
                    g_v[(bvp + d) * SEQ + ps0]     = __float2half_rn(x00);
                    g_v[(bvp + d + 1) * SEQ + ps0] = __float2half_rn(x01);
                    g_v[(bvp + d) * SEQ + ps1]     = __float2half_rn(x10);
                    g_v[(bvp + d + 1) * SEQ + ps1] = __float2half_rn(x11);
                } else {
                    uint32_t* dst = (uint32_t*)((z == 0) ? g_q : g_k);
                    int du = d >> 1;
                    int pu = (du & ~7) | PI8(du & 7);
                    size_t wbase = ((size_t)(bb * NHEADS + h) * SEQ + s) * (DKH / 2);
                    dst[wbase + pu]                = pack2(x00, x01);
                    dst[wbase + 8 * (DKH / 2) + pu] = pack2(x10, x11);
                }
            } else {
                *(float2*)&OutP[(size_t)row * DMODEL + col] = make_float2(x00, x01);
                *(float2*)&OutP[(size_t)(row + 8) * DMODEL + col] = make_float2(x10, x11);
            }
        }
    }
}

// ---------------------------------------------------------------------------
// Flash attention, fp16 m16n8k16: 128-row q tile, 4 warps x 32 rows,
// 3-stage cp.async (60KB -> 2 CTAs/SM). Q frags from GMEM; K [key][d]
// d-units PI8; V [d][key] key-units PI8; S C-frag packs directly into the
// P A-frag (half2); exp2-domain online softmax.
// ---------------------------------------------------------------------------
#define AAS 80                                   // halves per smem row
#define ASTG (2 * 64 * AAS)                      // halves per stage (K + V)
#define ATT_SMEM (3 * ASTG * 2)                  // 61440 B

__global__ __launch_bounds__(128, 2) void attn_kernel() {
    extern __shared__ __half sm[];

    const int tid = threadIdx.x;
    const int wid = tid >> 5, lane = tid & 31;
    const int g = lane >> 2, tg = lane & 3;
    const int bh = blockIdx.y;
    const int q0 = blockIdx.x * 128;

    const __half* Kg = g_k + (size_t)bh * SEQ * DKH;
    const __half* Vg = g_v + (size_t)bh * DKH * SEQ;

    // Q A-fragments straight from gmem (d-units PI8, prescaled)
    uint32_t qa[2][4][4];
    {
        const uint32_t* Qw = (const uint32_t*)g_q + ((size_t)bh * SEQ + q0 + wid * 32) * (DKH / 2);
#pragma unroll
        for (int mt = 0; mt < 2; mt++) {
#pragma unroll
            for (int ks = 0; ks < 4; ks++) {
                uint2 t0 = *(const uint2*)&Qw[(mt * 16 + g) * 32 + ks * 8 + 2 * tg];
                uint2 t1 = *(const uint2*)&Qw[(mt * 16 + 8 + g) * 32 + ks * 8 + 2 * tg];
                qa[mt][ks][0] = t0.x; qa[mt][ks][1] = t1.x;
                qa[mt][ks][2] = t0.y; qa[mt][ks][3] = t1.y;
            }
        }
    }

    float o[2][8][4];
#pragma unroll
    for (int mt = 0; mt < 2; mt++)
#pragma unroll
        for (int nt = 0; nt < 8; nt++)
#pragma unroll
            for (int i = 0; i < 4; i++) o[mt][nt][i] = 0.f;
    float mrow[2][2] = {{-1e30f, -1e30f}, {-1e30f, -1e30f}};
    float lrow[2][2] = {{0.f, 0.f}, {0.f, 0.f}};

    auto load_kv = [&](int kt, int st) {
        __half* Kd = sm + st * ASTG;
        __half* Vd = Kd + 64 * AAS;
#pragma unroll
        for (int i = 0; i < 4; i++) {
            int lin = tid + i * 128;
            int r = lin >> 3, c = (lin & 7) * 8;
            cp16(&Kd[r * AAS + c], Kg + (size_t)(kt * 64 + r) * DKH + c);
            cp16(&Vd[r * AAS + c], Vg + (size_t)r * SEQ + kt * 64 + c);
        }
        cp_commit();
    };

    const int NT = SEQ / 64;  // 64
    load_kv(0, 0);
    load_kv(1, 1);

    int cur = 0, nxt = 2;
    for (int kt = 0; kt < NT; kt++) {
        cp_wait<1>();
        __syncthreads();  // stage `cur` visible; stage `nxt` free (kt-1 compute done)
        if (kt + 2 < NT) load_kv(kt + 2, nxt);
        else cp_commit();

        const uint32_t* Ku = (const uint32_t*)(sm + cur * ASTG);
        const uint32_t* Vu = Ku + 64 * (AAS / 2);
        cur = (cur == 2) ? 0 : cur + 1;
        nxt = (nxt == 2) ? 0 : nxt + 1;

        // S = Q K^T (log2 domain via Q prescale)
        float sc[2][8][4];
#pragma unroll
        for (int mt = 0; mt < 2; mt++)
#pragma unroll
            for (int nt = 0; nt < 8; nt++)
#pragma unroll
                for (int i = 0; i < 4; i++) sc[mt][nt][i] = 0.f;
#pragma unroll
        for (int nt = 0; nt < 8; nt++) {
#pragma unroll
            for (int ks = 0; ks < 4; ks++) {
                uint2 bv = *(const uint2*)&Ku[(nt * 8 + g) * 40 + ks * 8 + 2 * tg];
                mma16(sc[0][nt], qa[0][ks], bv.x, bv.y);
                mma16(sc[1][nt], qa[1][ks], bv.x, bv.y);
            }
        }

        // row max + rescale (rows g / g+8 per m-subtile)
        float mn[2][2], alv[2][2];
#pragma unroll
        for (int mt = 0; mt < 2; mt++) {
            float mx0 = -1e30f, mx1 = -1e30f;
#pragma unroll
            for (int nt = 0; nt < 8; nt++) {
                mx0 = fmaxf(mx0, fmaxf(sc[mt][nt][0], sc[mt][nt][1]));
                mx1 = fmaxf(mx1, fmaxf(sc[mt][nt][2], sc[mt][nt][3]));
            }
            mx0 = fmaxf(mx0, __shfl_xor_sync(0xffffffffu, mx0, 1));
            mx0 = fmaxf(mx0, __shfl_xor_sync(0xffffffffu, mx0, 2));
            mx1 = fmaxf(mx1, __shfl_xor_sync(0xffffffffu, mx1, 1));
            mx1 = fmaxf(mx1, __shfl_xor_sync(0xffffffffu, mx1, 2));
            mn[mt][0] = fmaxf(mrow[mt][0], mx0);
            mn[mt][1] = fmaxf(mrow[mt][1], mx1);
            alv[mt][0] = ex2(mrow[mt][0] - mn[mt][0]);
            alv[mt][1] = ex2(mrow[mt][1] - mn[mt][1]);
            mrow[mt][0] = mn[mt][0];
            mrow[mt][1] = mn[mt][1];
#pragma unroll
            for (int nt = 0; nt < 8; nt++) {
                o[mt][nt][0] *= alv[mt][0];
                o[mt][nt][1] *= alv[mt][0];
                o[mt][nt][2] *= alv[mt][1];
                o[mt][nt][3] *= alv[mt][1];
            }
        }

        // exp + PV per 16-key chunk j; S C-frags (nt=2j, 2j+1) pack into A-frag
        float rs[2][2] = {{0.f, 0.f}, {0.f, 0.f}};
#pragma unroll
        for (int j = 0; j < 4; j++) {
            uint32_t pa[2][4];
#pragma unroll
            for (int mt = 0; mt < 2; mt++) {
                float e00 = ex2(sc[mt][2 * j][0] - mn[mt][0]);
                float e01 = ex2(sc[mt][2 * j][1] - mn[mt][0]);
                float e02 = ex2(sc[mt][2 * j][2] - mn[mt][1]);
                float e03 = ex2(sc[mt][2 * j][3] - mn[mt][1]);
                float e10 = ex2(sc[mt][2 * j + 1][0] - mn[mt][0]);
                float e11 = ex2(sc[mt][2 * j + 1][1] - mn[mt][0]);
                float e12 = ex2(sc[mt][2 * j + 1][2] - mn[mt][1]);
                float e13 = ex2(sc[mt][2 * j + 1][3] - mn[mt][1]);
                rs[mt][0] += e00 + e01 + e10 + e11;
                rs[mt][1] += e02 + e03 + e12 + e13;
                pa[mt][0] = pack2(e00, e01);  // row g,   keys 16j+2tg,+1
                pa[mt][1] = pack2(e02, e03);  // row g+8, keys 16j+2tg,+1
                pa[mt][2] = pack2(e10, e11);  // row g,   keys 16j+8+2tg,+1
                pa[mt][3] = pack2(e12, e13);  // row g+8, keys 16j+8+2tg,+1
            }
#pragma unroll
            for (int nt = 0; nt < 8; nt++) {
                uint2 bv = *(const uint2*)&Vu[(nt * 8 + g) * 40 + j * 8 + 2 * tg];
                mma16(o[0][nt], pa[0], bv.x, bv.y);
                mma16(o[1][nt], pa[1], bv.x, bv.y);
            }
        }
#pragma unroll
        for (int mt = 0; mt < 2; mt++) {
            float r0 = rs[mt][0], r1 = rs[mt][1];
            r0 += __shfl_xor_sync(0xffffffffu, r0, 1);
            r0 += __shfl_xor_sync(0xffffffffu, r0, 2);
            r1 += __shfl_xor_sync(0xffffffffu, r1, 1);
            r1 += __shfl_xor_sync(0xffffffffu, r1, 2);
            lrow[mt][0] = lrow[mt][0] * alv[mt][0] + r0;
            lrow[mt][1] = lrow[mt][1] * alv[mt][1] + r1;
        }
    }

    // finalize: ctx [B,S,D] fp16, k-unit PI8 (feeds out-proj GEMM A)
    const int bb = bh / NHEADS, h = bh % NHEADS;
#pragma unroll
    for (int mt = 0; mt < 2; mt++) {
        const float inv0 = 1.f / lrow[mt][0], inv1 = 1.f / lrow[mt][1];
        const int s0 = q0 + wid * 32 + mt * 16 + g;
#pragma unroll
        for (int nt = 0; nt < 8; nt++) {
            int col = h * 64 + nt * 8 + 2 * tg;  // even
            int u = col >> 1;
            int pu = (u & ~7) | PI8(u & 7);
            uint32_t* r0p = (uint32_t*)g_ctx + ((size_t)(bb * SEQ + s0)) * (DMODEL / 2);
            uint32_t* r1p = (uint32_t*)g_ctx + ((size_t)(bb * SEQ + s0 + 8)) * (DMODEL / 2);
            r0p[pu] = pack2(o[mt][nt][0] * inv0, o[mt][nt][1] * inv0);
            r1p[pu] = pack2(o[mt][nt][2] * inv1, o[mt][nt][3] * inv1);
        }
    }
}

// ---------------------------------------------------------------------------
extern "C" void kernel_launch(void* const* d_in, const int* in_sizes, int n_in,
                              void* d_out, int out_size) {
    const float* x  = (const float*)d_in[0];
    const float* wq = (const float*)d_in[1];
    const float* bq = (const float*)d_in[2];
    const float* wk = (const float*)d_in[3];
    const float* bk = (const float*)d_in[4];
    const float* wv = (const float*)d_in[5];
    const float* bv = (const float*)d_in[6];
    const float* wo = (const float*)d_in[7];
    const float* bo = (const float*)d_in[8];
    float* out = (float*)d_out;

    static bool attr_done = false;
    if (!attr_done) {
        cudaFuncSetAttribute(gemm_kernel<0>, cudaFuncAttributeMaxDynamicSharedMemorySize, GEMM_SMEM);
        cudaFuncSetAttribute(gemm_kernel<1>, cudaFuncAttributeMaxDynamicSharedMemorySize, GEMM_SMEM);
        cudaFuncSetAttribute(attn_kernel, cudaFuncAttributeMaxDynamicSharedMemorySize, ATT_SMEM);
        attr_done = true;
    }

    // 0) fp16 convert + permute + weight transpose
    {
        const long NX16 = MTOT * DMODEL / 16;
        const long NWT  = (long)DMODEL * (DMODEL / 16);
        long total = NX16 + 4 * NWT;
        cvt_kernel<<<(int)((total + 255) / 256), 256>>>(x, wq, wk, wv, wo);
    }

    // 1) fused QKV projection
    gemm_kernel<0><<<dim3(DMODEL / 128, MTOT / 128, 3), 256, GEMM_SMEM>>>(bq, bk, bv, nullptr);

    // 2) flash attention -> g_ctx
    attn_kernel<<<dim3(SEQ / 128, NB * NHEADS), 128, ATT_SMEM>>>();

    // 3) output projection -> d_out (fp32)
    gemm_kernel<1><<<dim3(DMODEL / 128, MTOT / 128, 1), 256, GEMM_SMEM>>>(bo, nullptr, nullptr, out);
}